// round 17
// baseline (speedup 1.0000x reference)
#include <cuda_runtime.h>

#define NMAX 100000
#define EMAX 3200000

// -------- device scratch (no allocations allowed) --------
// g_deg is zeroed at the END of each call (k_logits); zero-init at load.
__device__ int   g_deg[NMAX];          // per-node in-degree (excl self-loop)
__device__ int   g_start[NMAX];        // CSR row start
__device__ int   g_bsum[512];          // block sums for scan
__device__ int   g_rank[EMAX];         // per-edge rank within its dst (from deg_acc)
__device__ int   g_adj[EMAX];          // CSR adjacency: src indices grouped by dst
__device__ float g_dinv[NMAX];         // 1/sqrt(deg+1)
__device__ __align__(16) float g_ht1[NMAX * 16];   // raw x@W1, then dinv-scaled
__device__ __align__(16) float g_ht2[NMAX * 16];   // dinv * relu(agg1+b1)
__device__ float g_s1[NMAX];           // z . We[:64]
__device__ float g_s2[NMAX];           // z . We[64:]
__device__ float g_v1[16];             // W2 @ We[:64]
__device__ float g_v2[16];             // W2 @ We[64:]
__device__ float g_c1, g_c2;           // b2 . We halves

// -------- degree histogram (rank capture) + (block 0) fold W2/b2 head --------
__global__ void k_deg_acc(const int* __restrict__ dst, int E, int n,
                          const float* __restrict__ W2, const float* __restrict__ b2,
                          const float* __restrict__ We) {
    if (blockIdx.x == 0) {
        int t = threadIdx.x;
        if (t < 16) {
            float a = 0.f, b = 0.f;
            #pragma unroll
            for (int j = 0; j < 64; j++) {
                float w = W2[t * 64 + j];
                a += w * We[j];
                b += w * We[64 + j];
            }
            g_v1[t] = a;
            g_v2[t] = b;
        } else if (t == 16) {
            float a = 0.f, b = 0.f;
            #pragma unroll
            for (int j = 0; j < 64; j++) {
                a += b2[j] * We[j];
                b += b2[j] * We[64 + j];
            }
            g_c1 = a;
            g_c2 = b;
        }
    }
    int e = blockIdx.x * blockDim.x + threadIdx.x;
    if (e < E) {
        unsigned d = (unsigned)dst[e];
        if (d < (unsigned)n)
            g_rank[e] = atomicAdd(&g_deg[d], 1);   // rank within dst, coalesced store
    }
}

// per-block exclusive scan of g_deg -> g_start (block-local), totals -> g_bsum
__global__ void k_scan1(int n) {
    __shared__ int s[256];
    int tid = threadIdx.x;
    int i = blockIdx.x * 256 + tid;
    int v = (i < n) ? g_deg[i] : 0;
    s[tid] = v;
    __syncthreads();
    #pragma unroll
    for (int o = 1; o < 256; o <<= 1) {
        int t = (tid >= o) ? s[tid - o] : 0;
        __syncthreads();
        s[tid] += t;
        __syncthreads();
    }
    if (i < n) g_start[i] = s[tid] - v;
    if (tid == 255) g_bsum[blockIdx.x] = s[255];
}

// each block self-computes its prefix over bsum[0..b-1], finalizes starts/dinv
__global__ void k_scan23(int n) {
    __shared__ int red[256];
    int tid = threadIdx.x;
    int b = blockIdx.x;
    int partial = 0;
    for (int j = tid; j < b; j += 256) partial += g_bsum[j];
    red[tid] = partial;
    __syncthreads();
    #pragma unroll
    for (int o = 128; o > 0; o >>= 1) {
        if (tid < o) red[tid] += red[tid + o];
        __syncthreads();
    }
    int run = red[0];
    int i = b * 256 + tid;
    if (i < n) {
        g_start[i] = g_start[i] + run;
        g_dinv[i] = rsqrtf((float)g_deg[i] + 1.0f);   // +1 = self-loop
    }
}

// -------- atomic-free fill: slot = start[dst] + rank[e] --------
__global__ void k_fill(const int* __restrict__ src, const int* __restrict__ dst,
                       int E, int n) {
    int e = blockIdx.x * blockDim.x + threadIdx.x;
    if (e >= E) return;
    unsigned s = (unsigned)src[e];
    unsigned d = (unsigned)dst[e];
    if (s >= (unsigned)n || d >= (unsigned)n) return;
    int slot = __ldg(&g_start[d]) + g_rank[e];
    g_adj[slot] = (int)s;
}

// -------- GEMM1: ht1 = x @ W1 (raw), coalesced via smem x-tiles --------
__global__ void __launch_bounds__(256) k_gemm1(const float* __restrict__ x,
                                               const float* __restrict__ W1, int n) {
    __shared__ float4 Wss[2048];        // W1[k][4q..4q+3] (32 KB)
    __shared__ float  xs[256 * 12];     // 12 KB padded x tile
    for (int i = threadIdx.x; i < 2048; i += 256)
        Wss[i] = ((const float4*)W1)[i];

    int row0 = blockIdx.x * 256;
    int tid = threadIdx.x;

    float acc[16];
    #pragma unroll
    for (int j = 0; j < 16; j++) acc[j] = 0.f;

    const float4* xq = (const float4*)x;

    for (int kt = 0; kt < 64; kt++) {
        __syncthreads();
        #pragma unroll
        for (int m = 0; m < 2; m++) {
            int idx = tid + m * 256;
            int rr = idx >> 1, q = idx & 1;
            int grow = row0 + rr;
            float4 v = make_float4(0.f, 0.f, 0.f, 0.f);
            if (grow < n) v = __ldg(&xq[(size_t)grow * 128 + kt * 2 + q]);
            *(float4*)&xs[rr * 12 + q * 4] = v;
        }
        __syncthreads();

        float4 x0 = *(const float4*)&xs[tid * 12];
        float4 x1 = *(const float4*)&xs[tid * 12 + 4];
        float xv[8] = {x0.x, x0.y, x0.z, x0.w, x1.x, x1.y, x1.z, x1.w};
        #pragma unroll
        for (int kk = 0; kk < 8; kk++) {
            int k = kt * 8 + kk;
            float xsv = xv[kk];
            #pragma unroll
            for (int q2 = 0; q2 < 4; q2++) {
                float4 w = Wss[k * 4 + q2];
                acc[q2 * 4 + 0] = fmaf(xsv, w.x, acc[q2 * 4 + 0]);
                acc[q2 * 4 + 1] = fmaf(xsv, w.y, acc[q2 * 4 + 1]);
                acc[q2 * 4 + 2] = fmaf(xsv, w.z, acc[q2 * 4 + 2]);
                acc[q2 * 4 + 3] = fmaf(xsv, w.w, acc[q2 * 4 + 3]);
            }
        }
    }

    int r = row0 + tid;
    if (r < n) {
        float4* hp = (float4*)(g_ht1 + (size_t)r * 16);
        #pragma unroll
        for (int q = 0; q < 4; q++)
            hp[q] = make_float4(acc[q * 4 + 0], acc[q * 4 + 1],
                                acc[q * 4 + 2], acc[q * 4 + 3]);
    }
}

// -------- scale: ht1 *= dinv (side stream; overlaps k_fill) --------
__global__ void k_scale(int n) {
    int i = blockIdx.x * blockDim.x + threadIdx.x;
    if (i >= n) return;
    float di = g_dinv[i];
    float4* p = (float4*)(g_ht1 + (size_t)i * 16);
    #pragma unroll
    for (int q = 0; q < 4; q++) {
        float4 v = p[q];
        p[q] = make_float4(v.x * di, v.y * di, v.z * di, v.w * di);
    }
}

// -------- gather core: 4 lanes per node, one float4 (16B quarter-row) per lane ----
// Per edge the 4-lane group issues ONE LDG.128 each covering the full 64B row;
// warp covers 8 nodes -> 4x fewer LDG instructions than the 16-lane scalar form.
__device__ __forceinline__ float4 gather_feat4(const float4* __restrict__ ht4,
                                               int d, int l) {
    float4 acc = __ldg(&ht4[(d << 2) | l]);   // self-loop term
    int e = g_start[d];
    int end = e + g_deg[d];
    for (; e + 7 < end; e += 8) {
        int s0 = __ldg(&g_adj[e]);
        int s1 = __ldg(&g_adj[e + 1]);
        int s2 = __ldg(&g_adj[e + 2]);
        int s3 = __ldg(&g_adj[e + 3]);
        int s4 = __ldg(&g_adj[e + 4]);
        int s5 = __ldg(&g_adj[e + 5]);
        int s6 = __ldg(&g_adj[e + 6]);
        int s7 = __ldg(&g_adj[e + 7]);
        float4 v0 = __ldg(&ht4[(s0 << 2) | l]);
        float4 v1 = __ldg(&ht4[(s1 << 2) | l]);
        float4 v2 = __ldg(&ht4[(s2 << 2) | l]);
        float4 v3 = __ldg(&ht4[(s3 << 2) | l]);
        float4 v4 = __ldg(&ht4[(s4 << 2) | l]);
        float4 v5 = __ldg(&ht4[(s5 << 2) | l]);
        float4 v6 = __ldg(&ht4[(s6 << 2) | l]);
        float4 v7 = __ldg(&ht4[(s7 << 2) | l]);
        acc.x += ((v0.x + v1.x) + (v2.x + v3.x)) + ((v4.x + v5.x) + (v6.x + v7.x));
        acc.y += ((v0.y + v1.y) + (v2.y + v3.y)) + ((v4.y + v5.y) + (v6.y + v7.y));
        acc.z += ((v0.z + v1.z) + (v2.z + v3.z)) + ((v4.z + v5.z) + (v6.z + v7.z));
        acc.w += ((v0.w + v1.w) + (v2.w + v3.w)) + ((v4.w + v5.w) + (v6.w + v7.w));
    }
    for (; e + 1 < end; e += 2) {
        int s0 = __ldg(&g_adj[e]);
        int s1 = __ldg(&g_adj[e + 1]);
        float4 v0 = __ldg(&ht4[(s0 << 2) | l]);
        float4 v1 = __ldg(&ht4[(s1 << 2) | l]);
        acc.x += v0.x + v1.x;
        acc.y += v0.y + v1.y;
        acc.z += v0.z + v1.z;
        acc.w += v0.w + v1.w;
    }
    if (e < end) {
        int s0 = __ldg(&g_adj[e]);
        float4 v0 = __ldg(&ht4[(s0 << 2) | l]);
        acc.x += v0.x; acc.y += v0.y; acc.z += v0.z; acc.w += v0.w;
    }
    return acc;
}

// -------- gather layer 1: ht2 = dinv * relu(dinv*sum + b1) --------
__global__ void k_gather1(const float* __restrict__ b1, int n) {
    int t = blockIdx.x * blockDim.x + threadIdx.x;
    int d = t >> 2, l = t & 3;
    if (d >= n) return;
    float4 acc = gather_feat4((const float4*)g_ht1, d, l);
    float di = g_dinv[d];
    float4 bb = __ldg(&((const float4*)b1)[l]);
    float4 h;
    h.x = fmaxf(fmaf(acc.x, di, bb.x), 0.f) * di;
    h.y = fmaxf(fmaf(acc.y, di, bb.y), 0.f) * di;
    h.z = fmaxf(fmaf(acc.z, di, bb.z), 0.f) * di;
    h.w = fmaxf(fmaf(acc.w, di, bb.w), 0.f) * di;
    ((float4*)g_ht2)[(d << 2) | l] = h;
}

// -------- gather layer 2 + fused epilogue: z, s1, s2 (shuffle exchange) --------
__global__ void k_gather2(const float* __restrict__ W2, const float* __restrict__ b2,
                          float* __restrict__ z, int n) {
    __shared__ float4 Ws[16 * 16];   // W2[k] column-quads (4 KB)
    __shared__ float4 bs[16];
    __shared__ float vs1[16], vs2[16];
    for (int i = threadIdx.x; i < 256; i += blockDim.x)
        Ws[i] = ((const float4*)W2)[i];
    if (threadIdx.x < 16) {
        bs[threadIdx.x] = ((const float4*)b2)[threadIdx.x];
        vs1[threadIdx.x] = g_v1[threadIdx.x];
        vs2[threadIdx.x] = g_v2[threadIdx.x];
    }
    __syncthreads();

    int t = blockIdx.x * blockDim.x + threadIdx.x;
    int d = t >> 2, l = t & 3;
    bool valid = (d < n);

    float4 acc = make_float4(0.f, 0.f, 0.f, 0.f);
    if (valid) {
        acc = gather_feat4((const float4*)g_ht2, d, l);
        float di = g_dinv[d];
        acc.x *= di; acc.y *= di; acc.z *= di; acc.w *= di;
    }

    // rebuild all 16 per-feature sums in every lane of the 4-lane group
    int w = threadIdx.x & 31;
    int base = w & 28;   // group's base lane within the warp
    float a[16];
    #pragma unroll
    for (int k = 0; k < 4; k++) {
        a[4 * k + 0] = __shfl_sync(0xffffffffu, acc.x, base + k, 32);
        a[4 * k + 1] = __shfl_sync(0xffffffffu, acc.y, base + k, 32);
        a[4 * k + 2] = __shfl_sync(0xffffffffu, acc.z, base + k, 32);
        a[4 * k + 3] = __shfl_sync(0xffffffffu, acc.w, base + k, 32);
    }

    if (!valid) return;

    // head scalars: lane 0 -> s1, lane 1 -> s2
    if (l == 0) {
        float s1 = g_c1;
        #pragma unroll
        for (int k = 0; k < 16; k++) s1 = fmaf(a[k], vs1[k], s1);
        g_s1[d] = s1;
    } else if (l == 1) {
        float s2 = g_c2;
        #pragma unroll
        for (int k = 0; k < 16; k++) s2 = fmaf(a[k], vs2[k], s2);
        g_s2[d] = s2;
    }

    // z columns [16l, 16l+16): four float4 quads per lane, coalesced per node
    float4* zp = (float4*)(z + (size_t)d * 64) + l * 4;
    #pragma unroll
    for (int q = 0; q < 4; q++) {
        int j4 = l * 4 + q;
        float4 accv = bs[j4];
        #pragma unroll
        for (int k = 0; k < 16; k++) {
            float4 wv = Ws[k * 16 + j4];
            accv.x = fmaf(a[k], wv.x, accv.x);
            accv.y = fmaf(a[k], wv.y, accv.y);
            accv.z = fmaf(a[k], wv.z, accv.z);
            accv.w = fmaf(a[k], wv.w, accv.w);
        }
        zp[q] = accv;
    }
}

// -------- edge logits: s1[src] + s2[dst] + be ; also re-zero g_deg --------
__global__ void k_logits(const int* __restrict__ ps, const int* __restrict__ pd,
                         const int* __restrict__ ns, const int* __restrict__ nd,
                         const float* __restrict__ be, float* __restrict__ out,
                         int P, int Ng, int n) {
    int i = blockIdx.x * blockDim.x + threadIdx.x;
    if (i < n) g_deg[i] = 0;           // prepare next call (invariant: zero at entry)
    if (i >= P + Ng) return;
    unsigned s, d;
    if (i < P) { s = (unsigned)ps[i]; d = (unsigned)pd[i]; }
    else       { s = (unsigned)ns[i - P]; d = (unsigned)nd[i - P]; }
    float v = __ldg(be);
    if (s < (unsigned)n) v += g_s1[s];
    if (d < (unsigned)n) v += g_s2[d];
    out[i] = v;
}

extern "C" void kernel_launch(void* const* d_in, const int* in_sizes, int n_in,
                              void* d_out, int out_size) {
    const float* x  = (const float*)d_in[0];
    const float* W1 = (const float*)d_in[1];
    const float* b1 = (const float*)d_in[2];
    const float* W2 = (const float*)d_in[3];
    const float* b2 = (const float*)d_in[4];
    const float* We = (const float*)d_in[5];
    const float* be = (const float*)d_in[6];
    const int* ei = (const int*)d_in[7];   // edge_index int32 [2, E]
    const int* pe = (const int*)d_in[8];   // pos_edge_index int32 [2, P]
    const int* ne = (const int*)d_in[9];   // neg_edge_index int32 [2, Ng]

    int n  = in_sizes[0] / 512;
    int E  = in_sizes[7] / 2;
    int P  = in_sizes[8] / 2;
    int Ng = in_sizes[9] / 2;

    float* z = (float*)d_out;                 // [n, 64]
    float* logits = z + (size_t)n * 64;       // [P + Ng]

    const int* src = ei;
    const int* dst = ei + E;

    int nb  = (n + 255) / 256;
    int eb  = (E + 255) / 256;
    int gb  = (4 * n + 255) / 256;            // 4 lanes per node
    int lb  = (P + Ng + 255) / 256;

    // One-time stream/event setup (outside capture: first call is uncaptured).
    static cudaStream_t s1 = nullptr;
    static cudaEvent_t evFork = nullptr, evScan = nullptr, evScale = nullptr;
    if (s1 == nullptr) {
        cudaStreamCreateWithFlags(&s1, cudaStreamNonBlocking);
        cudaEventCreateWithFlags(&evFork, cudaEventDisableTiming);
        cudaEventCreateWithFlags(&evScan, cudaEventDisableTiming);
        cudaEventCreateWithFlags(&evScale, cudaEventDisableTiming);
    }

    // Fork at t=0: GEMM1 (raw h, no dinv dependency) on side stream.
    cudaEventRecord(evFork, 0);
    cudaStreamWaitEvent(s1, evFork, 0);
    k_gemm1<<<nb, 256, 0, s1>>>(x, W1, n);

    // Main stream: CSR build (g_deg zero on entry, invariant).
    k_deg_acc<<<eb, 256>>>(dst, E, n, W2, b2, We);
    k_scan1<<<nb, 256>>>(n);
    k_scan23<<<nb, 256>>>(n);
    cudaEventRecord(evScan, 0);               // dinv/starts ready
    k_fill<<<eb, 256>>>(src, dst, E, n);      // atomic-free

    // Side stream: scale (needs gemm1 done + dinv), overlaps fill.
    cudaStreamWaitEvent(s1, evScan, 0);
    k_scale<<<nb, 256, 0, s1>>>(n);
    cudaEventRecord(evScale, s1);

    // Join: gathers need scaled ht1 (side) and adj (fill, main-ordered).
    cudaStreamWaitEvent(0, evScale, 0);
    k_gather1<<<gb, 256>>>(b1, n);
    k_gather2<<<gb, 256>>>(W2, b2, z, n);
    k_logits<<<lb, 256>>>(pe, pe + P, ne, ne + Ng, be, logits, P, Ng, n);
}